// round 8
// baseline (speedup 1.0000x reference)
#include <cuda_runtime.h>
#include <cuda_bf16.h>
#include <cstdint>
#include <math.h>

// ---------------------------------------------------------------------------
// Problem constants
// ---------------------------------------------------------------------------
#define VEG 4
#define WEA 8
#define HID 512
#define NB  256
#define T_HIST 150
#define T_FUT  50
#define HB (NB * HID)
#define XPW 64            // padded x width (12 real + 52 zeros)
#define GROW 2048         // gate rows (4*HID)
#define NTHREADS 512      // 16 warps per CTA

// ---------------------------------------------------------------------------
// Device scratch (static only)
// ---------------------------------------------------------------------------
__device__ __nv_bfloat16 g_xph[T_HIST * NB * XPW];
__device__ __nv_bfloat16 g_xpl[T_HIST * NB * XPW];
__device__ __nv_bfloat16 g_xdh[NB * XPW];
__device__ __nv_bfloat16 g_xdl[NB * XPW];
__device__ float g_pred[NB * VEG];
__device__ __nv_bfloat16 g_y0h[T_HIST * HB];   // layer0 outputs hi (h-chain)
__device__ __nv_bfloat16 g_y0l[T_HIST * HB];
__device__ __nv_bfloat16 g_zb[HB];             // bf16 zeros
__device__ float g_c0[HB];
__device__ float g_c1[HB];
__device__ __nv_bfloat16 g_h1h[2 * HB], g_h1l[2 * HB];
__device__ __nv_bfloat16 g_h0h[2 * HB], g_h0l[2 * HB];
__device__ float g_h1f[HB];
__device__ float g_h0f[HB];                    // sink for layer0 fp32 h
// reordered (row = u*4+g) hi/lo weights
__device__ __nv_bfloat16 g_w0h[GROW * HID], g_w0l[GROW * HID];        // Whh0
__device__ __nv_bfloat16 g_w1hh_h[GROW * HID], g_w1hh_l[GROW * HID];  // Whh1
__device__ __nv_bfloat16 g_w1ih_h[GROW * HID], g_w1ih_l[GROW * HID];  // Wih1
__device__ __nv_bfloat16 g_wx0h[GROW * XPW], g_wx0l[GROW * XPW];      // Wih0 padded
__device__ float g_br0[GROW], g_br1[GROW];

// ---------------------------------------------------------------------------
// Portable PTX helpers (sm_80+ only — this toolchain rejects sm_100a features)
// ---------------------------------------------------------------------------
__device__ __forceinline__ uint32_t smem_u32(const void* p) {
    uint32_t a;
    asm("{ .reg .u64 t; cvta.to.shared.u64 t, %1; cvt.u32.u64 %0, t; }"
        : "=r"(a) : "l"(p));
    return a;
}
#define CP_ASYNC16(dst, src) \
    asm volatile("cp.async.cg.shared.global [%0], [%1], 16;" \
                 :: "r"(dst), "l"(src) : "memory")
#define CP_COMMIT() asm volatile("cp.async.commit_group;" ::: "memory")
#define CP_WAIT1()  asm volatile("cp.async.wait_group 1;" ::: "memory")
#define CP_WAIT0()  asm volatile("cp.async.wait_group 0;" ::: "memory")

#define LDM4(r, addr) \
    asm volatile("ldmatrix.sync.aligned.m8n8.x4.shared.b16 {%0,%1,%2,%3}, [%4];" \
                 : "=r"((r)[0]), "=r"((r)[1]), "=r"((r)[2]), "=r"((r)[3]) \
                 : "r"(addr))

#define MMA16816(d, a, b0, b1) \
    asm volatile( \
        "mma.sync.aligned.m16n8k16.row.col.f32.bf16.bf16.f32 " \
        "{%0,%1,%2,%3}, {%4,%5,%6,%7}, {%8,%9}, {%0,%1,%2,%3};" \
        : "+f"((d)[0]), "+f"((d)[1]), "+f"((d)[2]), "+f"((d)[3]) \
        : "r"((a)[0]), "r"((a)[1]), "r"((a)[2]), "r"((a)[3]), \
          "r"(b0), "r"(b1))

// ---------------------------------------------------------------------------
// SMEM layout — 3-stage pipeline, CTA tile 128(batch) x 64(gate)
// ---------------------------------------------------------------------------
#define SM_STRIDE 72                        // bf16 elems/row (144B, conflict-free)
#define A_TILE_B (128 * SM_STRIDE * 2)      // 18432
#define B_TILE_B (64 * SM_STRIDE * 2)       // 9216
#define STAGE_B (2 * A_TILE_B + 2 * B_TILE_B)  // 55296
#define NSTAGE 3
#define OFF_AH 0
#define OFF_AL A_TILE_B
#define OFF_BH (2 * A_TILE_B)
#define OFF_BL (2 * A_TILE_B + B_TILE_B)
#define CS_STRIDE 68                        // fp32 C tile row stride (16B-aligned)
#define OFF_BIAS (NSTAGE * STAGE_B)         // 165888
#define SMEM_TOTAL (OFF_BIAS + 64 * 4 + 16) // ~166 KB (fits 227KB/CTA)

// ---------------------------------------------------------------------------
// Math helpers
// ---------------------------------------------------------------------------
__device__ __forceinline__ float sigmoidf_(float x) { return 1.0f / (1.0f + __expf(-x)); }
__device__ __forceinline__ float tanhf_(float x)    { return 2.0f / (1.0f + __expf(-2.0f * x)) - 1.0f; }
__device__ __forceinline__ void split2(float x, __nv_bfloat16& h, __nv_bfloat16& l) {
    h = __float2bfloat16(x);
    l = __float2bfloat16(x - __bfloat162float(h));
}

// ---------------------------------------------------------------------------
// prep: smoothing + padded-x hi/lo for encoder; decoder init at t=149
// ---------------------------------------------------------------------------
__global__ void prep_kernel(const float* __restrict__ veg,
                            const float* __restrict__ wh,
                            const float* __restrict__ wf,
                            __nv_bfloat16* __restrict__ xph,
                            __nv_bfloat16* __restrict__ xpl,
                            __nv_bfloat16* __restrict__ xdh,
                            __nv_bfloat16* __restrict__ xdl,
                            float* __restrict__ pred) {
    int b = threadIdx.x;
    int t = blockIdx.x;
    const int base = (t * NB + b) * XPW;
    float vs[VEG];
#pragma unroll
    for (int v = 0; v < VEG; v++) {
        float val = veg[b * (T_HIST * VEG) + t * VEG + v];
        float s = 0.f;
#pragma unroll
        for (int dt = -2; dt <= 2; dt++) {
            int tt = t + dt;
            if (tt >= 0 && tt < T_HIST) {
                float u = veg[b * (T_HIST * VEG) + tt * VEG + v];
                if (!isnan(u)) s += u;
            }
        }
        float sm = s * 0.2f;
        float outv = isnan(val) ? sm : val;
        if (isnan(outv)) outv = 0.f;
        vs[v] = outv;
        __nv_bfloat16 hh, ll; split2(outv, hh, ll);
        xph[base + v] = hh; xpl[base + v] = ll;
    }
#pragma unroll
    for (int k = 0; k < WEA; k++) {
        float w = wh[b * (T_HIST * WEA) + t * WEA + k];
        __nv_bfloat16 hh, ll; split2(w, hh, ll);
        xph[base + VEG + k] = hh; xpl[base + VEG + k] = ll;
    }
    __nv_bfloat16 z = __float2bfloat16(0.f);
    for (int c = VEG + WEA; c < XPW; c++) { xph[base + c] = z; xpl[base + c] = z; }

    if (t == T_HIST - 1) {
        int db = b * XPW;
#pragma unroll
        for (int v = 0; v < VEG; v++) {
            pred[b * VEG + v] = vs[v];
            __nv_bfloat16 hh, ll; split2(vs[v], hh, ll);
            xdh[db + v] = hh; xdl[db + v] = ll;
        }
#pragma unroll
        for (int k = 0; k < WEA; k++) {
            float w = wf[b * (T_FUT * WEA) + k];
            __nv_bfloat16 hh, ll; split2(w, hh, ll);
            xdh[db + VEG + k] = hh; xdl[db + VEG + k] = ll;
        }
        for (int c = VEG + WEA; c < XPW; c++) { xdh[db + c] = z; xdl[db + c] = z; }
    }
}

// ---------------------------------------------------------------------------
// weight prep: reorder rows to u*4+g, split hi/lo, pad Wih0 to 64 cols
// ---------------------------------------------------------------------------
__global__ void wprep_kernel(const float* __restrict__ Wih0, const float* __restrict__ Whh0,
                             const float* __restrict__ b0,   const float* __restrict__ Wih1,
                             const float* __restrict__ Whh1, const float* __restrict__ b1,
                             __nv_bfloat16* w0h, __nv_bfloat16* w0l,
                             __nv_bfloat16* w1hhh, __nv_bfloat16* w1hhl,
                             __nv_bfloat16* w1ihh, __nv_bfloat16* w1ihl,
                             __nv_bfloat16* wx0h, __nv_bfloat16* wx0l,
                             float* br0, float* br1) {
    int rn = blockIdx.x;                       // new row
    int orig = (rn & 3) * HID + (rn >> 2);     // g*512 + u
    for (int c = threadIdx.x; c < HID; c += blockDim.x) {
        __nv_bfloat16 hh, ll;
        split2(Whh0[orig * HID + c], hh, ll);
        w0h[rn * HID + c] = hh; w0l[rn * HID + c] = ll;
        split2(Whh1[orig * HID + c], hh, ll);
        w1hhh[rn * HID + c] = hh; w1hhl[rn * HID + c] = ll;
        split2(Wih1[orig * HID + c], hh, ll);
        w1ihh[rn * HID + c] = hh; w1ihl[rn * HID + c] = ll;
    }
    if (threadIdx.x < XPW) {
        int c = threadIdx.x;
        float v = (c < VEG + WEA) ? Wih0[orig * (VEG + WEA) + c] : 0.f;
        __nv_bfloat16 hh, ll; split2(v, hh, ll);
        wx0h[rn * XPW + c] = hh; wx0l[rn * XPW + c] = ll;
    }
    if (threadIdx.x == 0) { br0[rn] = b0[orig]; br1[rn] = b1[orig]; }
}

__global__ void zero_kernel(float* __restrict__ c0, float* __restrict__ c1,
                            __nv_bfloat16* __restrict__ zb) {
    int i = blockIdx.x * blockDim.x + threadIdx.x;
    if (i < HB) { c0[i] = 0.f; c1[i] = 0.f; zb[i] = __float2bfloat16(0.f); }
}

// ---------------------------------------------------------------------------
// Cell body: one 128(batch)x64(gate) tile of a fused LSTM step on HMMA.
// 16 warps (4x4 warp grid, warp tile 32x16) for latency hiding.
// bf16 hi/lo 3-pass, 3-stage cp.async pipeline, dual accumulators.
// ---------------------------------------------------------------------------
__device__ __forceinline__ void cell_body(
    char* smem, int m0, int tileY,
    const __nv_bfloat16* __restrict__ AhH, const __nv_bfloat16* __restrict__ AhL,
    const __nv_bfloat16* __restrict__ BhH, const __nv_bfloat16* __restrict__ BhL,
    const __nv_bfloat16* __restrict__ AxH, const __nv_bfloat16* __restrict__ AxL,
    const __nv_bfloat16* __restrict__ BxH, const __nv_bfloat16* __restrict__ BxL,
    int ncx, int ldx,
    const float* __restrict__ biasr,
    float* __restrict__ c, float* __restrict__ hf,
    __nv_bfloat16* __restrict__ hhi, __nv_bfloat16* __restrict__ hlo) {

    const uint32_t sbase = smem_u32(smem);
    const int tid = threadIdx.x;
    const int warp = tid >> 5;
    const int lane = tid & 31;
    const int n0 = tileY * 64;        // reordered weight row base
    const int u0 = tileY * 16;        // unit base
    const int wm = warp >> 2;         // 0..3  (M 32-row slices)
    const int wn = warp & 3;          // 0..3  (N 16-col slices)

    if (tid < 64)
        *reinterpret_cast<float*>(smem + OFF_BIAS + tid * 4) = biasr[n0 + tid];

    float cfr[2][2][4];   // hi*hi
    float cfl[2][2][4];   // hi*lo + lo*hi
#pragma unroll
    for (int mi = 0; mi < 2; mi++)
#pragma unroll
        for (int nj = 0; nj < 2; nj++)
#pragma unroll
            for (int r = 0; r < 4; r++) { cfr[mi][nj][r] = 0.f; cfl[mi][nj][r] = 0.f; }

    const int NC = 8 + ncx;

    auto prefetch = [&](int ch) {
        const __nv_bfloat16 *aH, *aL, *bH, *bL;
        int lda, k0;
        if (ch < 8) { aH = AhH; aL = AhL; bH = BhH; bL = BhL; lda = HID; k0 = ch * 64; }
        else        { aH = AxH; aL = AxL; bH = BxH; bL = BxL; lda = ldx; k0 = (ch - 8) * 64; }
        const uint32_t st = sbase + (ch % NSTAGE) * STAGE_B;
        // A: 128 rows x 64 bf16 = 1024 x 16B, hi + lo
#pragma unroll
        for (int i = 0; i < 2; i++) {
            int idx = tid + i * NTHREADS;
            int r = idx >> 3, q = idx & 7;
            uint32_t off = r * (SM_STRIDE * 2) + q * 16;
            long ao = (long)(m0 + r) * lda + k0 + q * 8;
            CP_ASYNC16(st + OFF_AH + off, aH + ao);
            CP_ASYNC16(st + OFF_AL + off, aL + ao);
        }
        // B: 64 rows x 64 bf16 = 512 x 16B, hi + lo
        {
            int r = tid >> 3, q = tid & 7;
            uint32_t off = r * (SM_STRIDE * 2) + q * 16;
            long bo = (long)(n0 + r) * lda + k0 + q * 8;
            CP_ASYNC16(st + OFF_BH + off, bH + bo);
            CP_ASYNC16(st + OFF_BL + off, bL + bo);
        }
    };

    prefetch(0); CP_COMMIT();
    prefetch(1); CP_COMMIT();

    for (int ch = 0; ch < NC; ch++) {
        if (ch + 1 < NC) CP_WAIT1(); else CP_WAIT0();
        __syncthreads();                    // publishes chunk ch, frees stage (ch+2)%3
        if (ch + 2 < NC) { prefetch(ch + 2); CP_COMMIT(); }

        const uint32_t base = sbase + (ch % NSTAGE) * STAGE_B;
#pragma unroll
        for (int kk = 0; kk < 64; kk += 16) {
            uint32_t ah[2][4], al[2][4], bh[2][2], bl[2][2];
#pragma unroll
            for (int mi = 0; mi < 2; mi++) {
                uint32_t roff =
                    (uint32_t)((wm * 32 + mi * 16 + (lane & 15)) * (SM_STRIDE * 2) +
                               (kk + (lane >> 4) * 8) * 2);
                LDM4(ah[mi], base + OFF_AH + roff);
                LDM4(al[mi], base + OFF_AL + roff);
            }
            {
                uint32_t roff =
                    (uint32_t)((wn * 16 + (lane & 15)) * (SM_STRIDE * 2) +
                               (kk + (lane >> 4) * 8) * 2);
                uint32_t rb[4], rl[4];
                LDM4(rb, base + OFF_BH + roff);
                LDM4(rl, base + OFF_BL + roff);
                bh[0][0] = rb[0]; bh[0][1] = rb[2];
                bh[1][0] = rb[1]; bh[1][1] = rb[3];
                bl[0][0] = rl[0]; bl[0][1] = rl[2];
                bl[1][0] = rl[1]; bl[1][1] = rl[3];
            }
#pragma unroll
            for (int mi = 0; mi < 2; mi++)
#pragma unroll
                for (int nj = 0; nj < 2; nj++) {
                    MMA16816(cfr[mi][nj], ah[mi], bh[nj][0], bh[nj][1]);
                    MMA16816(cfl[mi][nj], ah[mi], bl[nj][0], bl[nj][1]);
                    MMA16816(cfl[mi][nj], al[mi], bh[nj][0], bh[nj][1]);
                }
        }
    }
    __syncthreads();   // all ldmatrix reads done before Cs overwrites stage 0

    // ---- epilogue: fragments -> smem C tile -> gate math ----
    float* Cs = reinterpret_cast<float*>(smem);   // 128 x CS_STRIDE fp32
#pragma unroll
    for (int mi = 0; mi < 2; mi++)
#pragma unroll
        for (int nj = 0; nj < 2; nj++) {
            int r = wm * 32 + mi * 16 + (lane >> 2);
            int col = wn * 16 + nj * 8 + (lane & 3) * 2;
            Cs[r * CS_STRIDE + col]           = cfr[mi][nj][0] + cfl[mi][nj][0];
            Cs[r * CS_STRIDE + col + 1]       = cfr[mi][nj][1] + cfl[mi][nj][1];
            Cs[(r + 8) * CS_STRIDE + col]     = cfr[mi][nj][2] + cfl[mi][nj][2];
            Cs[(r + 8) * CS_STRIDE + col + 1] = cfr[mi][nj][3] + cfl[mi][nj][3];
        }
    __syncthreads();

    const float* Bs = reinterpret_cast<const float*>(smem + OFF_BIAS);
#pragma unroll
    for (int k = 0; k < 4; k++) {
        int id = tid + k * NTHREADS;          // 0..2047
        int u = id & 15, bb = id >> 4;        // bb 0..127
        float4 g4 = *reinterpret_cast<const float4*>(&Cs[bb * CS_STRIDE + u * 4]);
        float gi = sigmoidf_(g4.x + Bs[u * 4 + 0]);
        float gf = sigmoidf_(g4.y + Bs[u * 4 + 1]);
        float gg = tanhf_   (g4.z + Bs[u * 4 + 2]);
        float go = sigmoidf_(g4.w + Bs[u * 4 + 3]);
        int gidx = (m0 + bb) * HID + u0 + u;
        float cn = gf * c[gidx] + gi * gg;
        c[gidx] = cn;
        float hv = go * tanhf_(cn);
        hf[gidx] = hv;
        __nv_bfloat16 hh, ll; split2(hv, hh, ll);
        hhi[gidx] = hh; hlo[gidx] = ll;
    }
}

// ---------------------------------------------------------------------------
// Single-cell kernel (decoder + encoder endpoints): grid (2, 32)
// ---------------------------------------------------------------------------
__global__ void __launch_bounds__(NTHREADS, 1)
cell_mma(const __nv_bfloat16* __restrict__ AhH, const __nv_bfloat16* __restrict__ AhL,
         const __nv_bfloat16* __restrict__ BhH, const __nv_bfloat16* __restrict__ BhL,
         const __nv_bfloat16* __restrict__ AxH, const __nv_bfloat16* __restrict__ AxL,
         const __nv_bfloat16* __restrict__ BxH, const __nv_bfloat16* __restrict__ BxL,
         int ncx, int ldx,
         const float* __restrict__ biasr,
         float* __restrict__ c, float* __restrict__ hf,
         __nv_bfloat16* __restrict__ hhi, __nv_bfloat16* __restrict__ hlo) {
    extern __shared__ __align__(16) char smem[];
    cell_body(smem, blockIdx.x * 128, blockIdx.y,
              AhH, AhL, BhH, BhL, AxH, AxL, BxH, BxL,
              ncx, ldx, biasr, c, hf, hhi, hlo);
}

// ---------------------------------------------------------------------------
// Merged encoder wavefront step: L1(t) on tiles y<32, L0(t+1) on tiles y>=32.
// grid (2, 64) = 128 CTAs -> one wave on 148 SMs.
// ---------------------------------------------------------------------------
__global__ void __launch_bounds__(NTHREADS, 1)
enc_step(// L1(t):
         const __nv_bfloat16* __restrict__ h1pH, const __nv_bfloat16* __restrict__ h1pL,
         const __nv_bfloat16* __restrict__ w1hhh, const __nv_bfloat16* __restrict__ w1hhl,
         const __nv_bfloat16* __restrict__ y0tH, const __nv_bfloat16* __restrict__ y0tL,
         const __nv_bfloat16* __restrict__ w1ihh, const __nv_bfloat16* __restrict__ w1ihl,
         const float* __restrict__ br1, float* __restrict__ c1,
         float* __restrict__ h1f,
         __nv_bfloat16* __restrict__ h1oh, __nv_bfloat16* __restrict__ h1ol,
         // L0(t+1):
         const __nv_bfloat16* __restrict__ xnH, const __nv_bfloat16* __restrict__ xnL,
         const __nv_bfloat16* __restrict__ w0h, const __nv_bfloat16* __restrict__ w0l,
         const __nv_bfloat16* __restrict__ wx0h, const __nv_bfloat16* __restrict__ wx0l,
         const float* __restrict__ br0, float* __restrict__ c0,
         float* __restrict__ h0f,
         __nv_bfloat16* __restrict__ y0nH, __nv_bfloat16* __restrict__ y0nL) {
    extern __shared__ __align__(16) char smem[];
    const int m0 = blockIdx.x * 128;
    if (blockIdx.y < 32) {
        // layer 1, step t: A = h1(t-1), X = y0(t)
        cell_body(smem, m0, blockIdx.y,
                  h1pH, h1pL, w1hhh, w1hhl, y0tH, y0tL, w1ihh, w1ihl,
                  8, HID, br1, c1, h1f, h1oh, h1ol);
    } else {
        // layer 0, step t+1: A = y0(t) (h-prev), X = xhist(t+1)
        cell_body(smem, m0, blockIdx.y - 32,
                  y0tH, y0tL, w0h, w0l, xnH, xnL, wx0h, wx0l,
                  1, XPW, br0, c0, h0f, y0nH, y0nL);
    }
}

// ---------------------------------------------------------------------------
// head: pred += h1 @ headW^T + headb ; write output[t]; build next decoder x
// ---------------------------------------------------------------------------
__global__ void head_kernel(const float* __restrict__ h1,
                            const float* __restrict__ headW,
                            const float* __restrict__ headb,
                            float* __restrict__ pred,
                            float* __restrict__ out_t,
                            const float* __restrict__ wf_next,
                            __nv_bfloat16* __restrict__ xdh,
                            __nv_bfloat16* __restrict__ xdl) {
    int b = blockIdx.x;
    int w = threadIdx.x >> 5;
    int lane = threadIdx.x & 31;
    const float* hr = &h1[b * HID];
    const float* wr = &headW[w * HID];
    float s = 0.f;
    for (int k = lane; k < HID; k += 32) s += hr[k] * wr[k];
#pragma unroll
    for (int o = 16; o; o >>= 1) s += __shfl_down_sync(0xffffffffu, s, o);
    if (lane == 0) {
        float p = pred[b * VEG + w] + s + headb[w];
        pred[b * VEG + w] = p;
        out_t[b * (T_FUT * VEG) + w] = p;
        __nv_bfloat16 hh, ll; split2(p, hh, ll);
        xdh[b * XPW + w] = hh; xdl[b * XPW + w] = ll;
    }
    if (threadIdx.x < WEA && wf_next) {
        float v = wf_next[b * (T_FUT * WEA) + threadIdx.x];
        __nv_bfloat16 hh, ll; split2(v, hh, ll);
        xdh[b * XPW + VEG + threadIdx.x] = hh;
        xdl[b * XPW + VEG + threadIdx.x] = ll;
    }
}

// ---------------------------------------------------------------------------
// Host launcher (single stream — graph-capture safe)
// ---------------------------------------------------------------------------
extern "C" void kernel_launch(void* const* d_in, const int* in_sizes, int n_in,
                              void* d_out, int out_size) {
    const float* veg   = (const float*)d_in[0];
    const float* wh    = (const float*)d_in[1];
    const float* wf    = (const float*)d_in[2];
    const float* Wih0  = (const float*)d_in[3];
    const float* Whh0  = (const float*)d_in[4];
    const float* b0    = (const float*)d_in[5];
    const float* Wih1  = (const float*)d_in[6];
    const float* Whh1  = (const float*)d_in[7];
    const float* b1    = (const float*)d_in[8];
    const float* headW = (const float*)d_in[9];
    const float* headb = (const float*)d_in[10];
    float* out = (float*)d_out;

    __nv_bfloat16 *xph, *xpl, *xdh, *xdl, *y0h, *y0l, *zb;
    __nv_bfloat16 *h1h, *h1l, *h0h, *h0l;
    __nv_bfloat16 *w0h, *w0l, *w1hhh, *w1hhl, *w1ihh, *w1ihl, *wx0h, *wx0l;
    float *pred, *c0, *c1, *h1f, *h0f, *br0, *br1;
    cudaGetSymbolAddress((void**)&xph,   g_xph);
    cudaGetSymbolAddress((void**)&xpl,   g_xpl);
    cudaGetSymbolAddress((void**)&xdh,   g_xdh);
    cudaGetSymbolAddress((void**)&xdl,   g_xdl);
    cudaGetSymbolAddress((void**)&pred,  g_pred);
    cudaGetSymbolAddress((void**)&y0h,   g_y0h);
    cudaGetSymbolAddress((void**)&y0l,   g_y0l);
    cudaGetSymbolAddress((void**)&zb,    g_zb);
    cudaGetSymbolAddress((void**)&c0,    g_c0);
    cudaGetSymbolAddress((void**)&c1,    g_c1);
    cudaGetSymbolAddress((void**)&h1h,   g_h1h);
    cudaGetSymbolAddress((void**)&h1l,   g_h1l);
    cudaGetSymbolAddress((void**)&h0h,   g_h0h);
    cudaGetSymbolAddress((void**)&h0l,   g_h0l);
    cudaGetSymbolAddress((void**)&h1f,   g_h1f);
    cudaGetSymbolAddress((void**)&h0f,   g_h0f);
    cudaGetSymbolAddress((void**)&w0h,   g_w0h);
    cudaGetSymbolAddress((void**)&w0l,   g_w0l);
    cudaGetSymbolAddress((void**)&w1hhh, g_w1hh_h);
    cudaGetSymbolAddress((void**)&w1hhl, g_w1hh_l);
    cudaGetSymbolAddress((void**)&w1ihh, g_w1ih_h);
    cudaGetSymbolAddress((void**)&w1ihl, g_w1ih_l);
    cudaGetSymbolAddress((void**)&wx0h,  g_wx0h);
    cudaGetSymbolAddress((void**)&wx0l,  g_wx0l);
    cudaGetSymbolAddress((void**)&br0,   g_br0);
    cudaGetSymbolAddress((void**)&br1,   g_br1);

    cudaFuncSetAttribute(cell_mma, cudaFuncAttributeMaxDynamicSharedMemorySize,
                         SMEM_TOTAL);
    cudaFuncSetAttribute(enc_step, cudaFuncAttributeMaxDynamicSharedMemorySize,
                         SMEM_TOTAL);

    dim3 grid1(2, 32), grid2(2, 64), blk(NTHREADS);

    prep_kernel<<<T_HIST, NB>>>(veg, wh, wf, xph, xpl, xdh, xdl, pred);
    wprep_kernel<<<GROW, 128>>>(Wih0, Whh0, b0, Wih1, Whh1, b1,
                                w0h, w0l, w1hhh, w1hhl, w1ihh, w1ihl,
                                wx0h, wx0l, br0, br1);
    zero_kernel<<<(HB + 255) / 256, 256>>>(c0, c1, zb);

    // L0(0) alone
    cell_mma<<<grid1, blk, SMEM_TOTAL>>>(
        zb, zb, w0h, w0l, xph, xpl, wx0h, wx0l,
        1, XPW, br0, c0, h0f, y0h, y0l);

    // merged wavefront: t = 0..148 computes L1(t) and L0(t+1) concurrently
    for (int t = 0; t < T_HIST - 1; t++) {
        const __nv_bfloat16* h1pH = (t == 0) ? zb : (h1h + ((t + 1) & 1) * HB);
        const __nv_bfloat16* h1pL = (t == 0) ? zb : (h1l + ((t + 1) & 1) * HB);
        enc_step<<<grid2, blk, SMEM_TOTAL>>>(
            h1pH, h1pL, w1hhh, w1hhl,
            y0h + (size_t)t * HB, y0l + (size_t)t * HB, w1ihh, w1ihl,
            br1, c1, h1f, h1h + (t & 1) * HB, h1l + (t & 1) * HB,
            xph + (size_t)(t + 1) * NB * XPW, xpl + (size_t)(t + 1) * NB * XPW,
            w0h, w0l, wx0h, wx0l,
            br0, c0, h0f,
            y0h + (size_t)(t + 1) * HB, y0l + (size_t)(t + 1) * HB);
    }
    // final L1(149): reads h1[148&1=0], writes h1[149&1=1]
    {
        int t = T_HIST - 1;
        cell_mma<<<grid1, blk, SMEM_TOTAL>>>(
            h1h + ((t + 1) & 1) * HB, h1l + ((t + 1) & 1) * HB, w1hhh, w1hhl,
            y0h + (size_t)t * HB, y0l + (size_t)t * HB, w1ihh, w1ihl,
            8, HID, br1, c1, h1f, h1h + (t & 1) * HB, h1l + (t & 1) * HB);
    }

    // decoder (serial dependence)
    // h1 ping-pong: encoder ended writing index 1 (t=149). Decoder step t
    // reads index (t+1)&1 and writes index t&1 (t=0: read 1, write 0).
    for (int t = 0; t < T_FUT; t++) {
        const __nv_bfloat16* hpH = (t == 0) ? (y0h + (size_t)(T_HIST - 1) * HB)
                                            : (h0h + ((t + 1) & 1) * HB);
        const __nv_bfloat16* hpL = (t == 0) ? (y0l + (size_t)(T_HIST - 1) * HB)
                                            : (h0l + ((t + 1) & 1) * HB);
        cell_mma<<<grid1, blk, SMEM_TOTAL>>>(
            hpH, hpL, w0h, w0l, xdh, xdl, wx0h, wx0l,
            1, XPW, br0, c0, h0f, h0h + (t & 1) * HB, h0l + (t & 1) * HB);
        cell_mma<<<grid1, blk, SMEM_TOTAL>>>(
            h1h + ((t + 1) & 1) * HB, h1l + ((t + 1) & 1) * HB, w1hhh, w1hhl,
            h0h + (t & 1) * HB, h0l + (t & 1) * HB, w1ihh, w1ihl,
            8, HID, br1, c1, h1f, h1h + (t & 1) * HB, h1l + (t & 1) * HB);
        const float* wfn = (t < T_FUT - 1) ? (wf + (t + 1) * WEA) : nullptr;
        head_kernel<<<NB, 128>>>(h1f, headW, headb, pred,
                                 out + t * VEG, wfn, xdh, xdl);
    }
}

// round 9
// speedup vs baseline: 1.1879x; 1.1879x over previous
#include <cuda_runtime.h>
#include <cuda_bf16.h>
#include <cstdint>
#include <math.h>

// ---------------------------------------------------------------------------
// Problem constants
// ---------------------------------------------------------------------------
#define VEG 4
#define WEA 8
#define HID 512
#define NB  256
#define T_HIST 150
#define T_FUT  50
#define HB (NB * HID)
#define XPW 64            // padded x width (12 real + 52 zeros)
#define GROW 2048         // gate rows (4*HID)
#define NTHREADS 512      // 16 warps per CTA

// ---------------------------------------------------------------------------
// Device scratch (static only)
// ---------------------------------------------------------------------------
__device__ __nv_bfloat16 g_xph[T_HIST * NB * XPW];
__device__ __nv_bfloat16 g_xpl[T_HIST * NB * XPW];
__device__ __nv_bfloat16 g_xdh[NB * XPW];
__device__ __nv_bfloat16 g_xdl[NB * XPW];
__device__ float g_pred[NB * VEG];
__device__ __nv_bfloat16 g_y0h[T_HIST * HB];   // layer0 outputs hi (h-chain)
__device__ __nv_bfloat16 g_y0l[T_HIST * HB];
__device__ __nv_bfloat16 g_zb[HB];             // bf16 zeros
__device__ float g_c0[HB];
__device__ float g_c1[HB];
__device__ __nv_bfloat16 g_h1h[2 * HB], g_h1l[2 * HB];
__device__ __nv_bfloat16 g_h0h[2 * HB], g_h0l[2 * HB];
__device__ float g_h1f[HB];
__device__ float g_h0f[HB];                    // sink for layer0 fp32 h
// reordered (row = u*4+g) hi/lo weights
__device__ __nv_bfloat16 g_w0h[GROW * HID], g_w0l[GROW * HID];        // Whh0
__device__ __nv_bfloat16 g_w1hh_h[GROW * HID], g_w1hh_l[GROW * HID];  // Whh1
__device__ __nv_bfloat16 g_w1ih_h[GROW * HID], g_w1ih_l[GROW * HID];  // Wih1
__device__ __nv_bfloat16 g_wx0h[GROW * XPW], g_wx0l[GROW * XPW];      // Wih0 padded
__device__ float g_br0[GROW], g_br1[GROW];

// ---------------------------------------------------------------------------
// Portable PTX helpers (sm_80+ only)
// ---------------------------------------------------------------------------
__device__ __forceinline__ uint32_t smem_u32(const void* p) {
    uint32_t a;
    asm("{ .reg .u64 t; cvta.to.shared.u64 t, %1; cvt.u32.u64 %0, t; }"
        : "=r"(a) : "l"(p));
    return a;
}
#define CP_ASYNC16(dst, src) \
    asm volatile("cp.async.cg.shared.global [%0], [%1], 16;" \
                 :: "r"(dst), "l"(src) : "memory")
#define CP_COMMIT() asm volatile("cp.async.commit_group;" ::: "memory")
#define CP_WAIT1()  asm volatile("cp.async.wait_group 1;" ::: "memory")
#define CP_WAIT0()  asm volatile("cp.async.wait_group 0;" ::: "memory")

#define LDM4(r, addr) \
    asm volatile("ldmatrix.sync.aligned.m8n8.x4.shared.b16 {%0,%1,%2,%3}, [%4];" \
                 : "=r"((r)[0]), "=r"((r)[1]), "=r"((r)[2]), "=r"((r)[3]) \
                 : "r"(addr))

#define MMA16816(d, a, b0, b1) \
    asm volatile( \
        "mma.sync.aligned.m16n8k16.row.col.f32.bf16.bf16.f32 " \
        "{%0,%1,%2,%3}, {%4,%5,%6,%7}, {%8,%9}, {%0,%1,%2,%3};" \
        : "+f"((d)[0]), "+f"((d)[1]), "+f"((d)[2]), "+f"((d)[3]) \
        : "r"((a)[0]), "r"((a)[1]), "r"((a)[2]), "r"((a)[3]), \
          "r"(b0), "r"(b1))

// ---------------------------------------------------------------------------
// SMEM layout (parameterized by M tile)
// ---------------------------------------------------------------------------
#define SM_STRIDE 72                        // bf16 elems/row (144B, conflict-free)
#define ROW_B (SM_STRIDE * 2)               // 144 bytes
#define B_TILE_BYTES (64 * ROW_B)           // 9216
#define NSTAGE 3
#define CS_STRIDE 68                        // fp32 C tile row stride

#define A_TILE_BYTES_(MT) ((MT) * ROW_B)
#define STAGE_BYTES_(MT)  (2 * A_TILE_BYTES_(MT) + 2 * B_TILE_BYTES)
#define OFF_BIAS_(MT)     (NSTAGE * STAGE_BYTES_(MT))
#define SMEM_TOTAL_(MT)   (OFF_BIAS_(MT) + 64 * 4 + 16)
// MT=128: stage 55296, total 166160.  MT=64: stage 36864, total 110864.

// ---------------------------------------------------------------------------
// Math helpers
// ---------------------------------------------------------------------------
__device__ __forceinline__ float sigmoidf_(float x) { return 1.0f / (1.0f + __expf(-x)); }
__device__ __forceinline__ float tanhf_(float x)    { return 2.0f / (1.0f + __expf(-2.0f * x)) - 1.0f; }
__device__ __forceinline__ void split2(float x, __nv_bfloat16& h, __nv_bfloat16& l) {
    h = __float2bfloat16(x);
    l = __float2bfloat16(x - __bfloat162float(h));
}

// ---------------------------------------------------------------------------
// prep: smoothing + padded-x hi/lo for encoder; decoder init at t=149
// ---------------------------------------------------------------------------
__global__ void prep_kernel(const float* __restrict__ veg,
                            const float* __restrict__ wh,
                            const float* __restrict__ wf,
                            __nv_bfloat16* __restrict__ xph,
                            __nv_bfloat16* __restrict__ xpl,
                            __nv_bfloat16* __restrict__ xdh,
                            __nv_bfloat16* __restrict__ xdl,
                            float* __restrict__ pred) {
    int b = threadIdx.x;
    int t = blockIdx.x;
    const int base = (t * NB + b) * XPW;
    float vs[VEG];
#pragma unroll
    for (int v = 0; v < VEG; v++) {
        float val = veg[b * (T_HIST * VEG) + t * VEG + v];
        float s = 0.f;
#pragma unroll
        for (int dt = -2; dt <= 2; dt++) {
            int tt = t + dt;
            if (tt >= 0 && tt < T_HIST) {
                float u = veg[b * (T_HIST * VEG) + tt * VEG + v];
                if (!isnan(u)) s += u;
            }
        }
        float sm = s * 0.2f;
        float outv = isnan(val) ? sm : val;
        if (isnan(outv)) outv = 0.f;
        vs[v] = outv;
        __nv_bfloat16 hh, ll; split2(outv, hh, ll);
        xph[base + v] = hh; xpl[base + v] = ll;
    }
#pragma unroll
    for (int k = 0; k < WEA; k++) {
        float w = wh[b * (T_HIST * WEA) + t * WEA + k];
        __nv_bfloat16 hh, ll; split2(w, hh, ll);
        xph[base + VEG + k] = hh; xpl[base + VEG + k] = ll;
    }
    __nv_bfloat16 z = __float2bfloat16(0.f);
    for (int c = VEG + WEA; c < XPW; c++) { xph[base + c] = z; xpl[base + c] = z; }

    if (t == T_HIST - 1) {
        int db = b * XPW;
#pragma unroll
        for (int v = 0; v < VEG; v++) {
            pred[b * VEG + v] = vs[v];
            __nv_bfloat16 hh, ll; split2(vs[v], hh, ll);
            xdh[db + v] = hh; xdl[db + v] = ll;
        }
#pragma unroll
        for (int k = 0; k < WEA; k++) {
            float w = wf[b * (T_FUT * WEA) + k];
            __nv_bfloat16 hh, ll; split2(w, hh, ll);
            xdh[db + VEG + k] = hh; xdl[db + VEG + k] = ll;
        }
        for (int c = VEG + WEA; c < XPW; c++) { xdh[db + c] = z; xdl[db + c] = z; }
    }
}

// ---------------------------------------------------------------------------
// weight prep: reorder rows to u*4+g, split hi/lo, pad Wih0 to 64 cols
// ---------------------------------------------------------------------------
__global__ void wprep_kernel(const float* __restrict__ Wih0, const float* __restrict__ Whh0,
                             const float* __restrict__ b0,   const float* __restrict__ Wih1,
                             const float* __restrict__ Whh1, const float* __restrict__ b1,
                             __nv_bfloat16* w0h, __nv_bfloat16* w0l,
                             __nv_bfloat16* w1hhh, __nv_bfloat16* w1hhl,
                             __nv_bfloat16* w1ihh, __nv_bfloat16* w1ihl,
                             __nv_bfloat16* wx0h, __nv_bfloat16* wx0l,
                             float* br0, float* br1) {
    int rn = blockIdx.x;                       // new row
    int orig = (rn & 3) * HID + (rn >> 2);     // g*512 + u
    for (int c = threadIdx.x; c < HID; c += blockDim.x) {
        __nv_bfloat16 hh, ll;
        split2(Whh0[orig * HID + c], hh, ll);
        w0h[rn * HID + c] = hh; w0l[rn * HID + c] = ll;
        split2(Whh1[orig * HID + c], hh, ll);
        w1hhh[rn * HID + c] = hh; w1hhl[rn * HID + c] = ll;
        split2(Wih1[orig * HID + c], hh, ll);
        w1ihh[rn * HID + c] = hh; w1ihl[rn * HID + c] = ll;
    }
    if (threadIdx.x < XPW) {
        int c = threadIdx.x;
        float v = (c < VEG + WEA) ? Wih0[orig * (VEG + WEA) + c] : 0.f;
        __nv_bfloat16 hh, ll; split2(v, hh, ll);
        wx0h[rn * XPW + c] = hh; wx0l[rn * XPW + c] = ll;
    }
    if (threadIdx.x == 0) { br0[rn] = b0[orig]; br1[rn] = b1[orig]; }
}

__global__ void zero_kernel(float* __restrict__ c0, float* __restrict__ c1,
                            __nv_bfloat16* __restrict__ zb) {
    int i = blockIdx.x * blockDim.x + threadIdx.x;
    if (i < HB) { c0[i] = 0.f; c1[i] = 0.f; zb[i] = __float2bfloat16(0.f); }
}

// ---------------------------------------------------------------------------
// Cell body: one MT(batch)x64(gate) tile of a fused LSTM step on HMMA.
// 16 warps: (MT/32) M-slices x 2 N-slices x KS K-groups; warp tile 32x32.
// bf16 hi/lo 3-pass, 3-stage cp.async pipeline, K-group smem reduction.
// ---------------------------------------------------------------------------
template <int MT, int KS>
__device__ __forceinline__ void cell_body(
    char* smem, int m0, int tileY,
    const __nv_bfloat16* __restrict__ AhH, const __nv_bfloat16* __restrict__ AhL,
    const __nv_bfloat16* __restrict__ BhH, const __nv_bfloat16* __restrict__ BhL,
    const __nv_bfloat16* __restrict__ AxH, const __nv_bfloat16* __restrict__ AxL,
    const __nv_bfloat16* __restrict__ BxH, const __nv_bfloat16* __restrict__ BxL,
    int ncx, int ldx,
    const float* __restrict__ biasr,
    float* __restrict__ c, float* __restrict__ hf,
    __nv_bfloat16* __restrict__ hhi, __nv_bfloat16* __restrict__ hlo) {

    constexpr int A_TILE = A_TILE_BYTES_(MT);
    constexpr int STAGE  = STAGE_BYTES_(MT);
    constexpr int OFF_AH = 0;
    constexpr int OFF_AL = A_TILE;
    constexpr int OFF_BH = 2 * A_TILE;
    constexpr int OFF_BL = 2 * A_TILE + B_TILE_BYTES;
    constexpr int OFF_BIAS = OFF_BIAS_(MT);
    constexpr int WM = MT / 32;           // M warp-slices
    constexpr int KITER = 4 / KS;         // kk slices per warp per chunk
    static_assert(WM * 2 * KS == 16, "warp layout");

    const uint32_t sbase = smem_u32(smem);
    const int tid = threadIdx.x;
    const int warp = tid >> 5;
    const int lane = tid & 31;
    const int n0 = tileY * 64;            // reordered weight row base
    const int u0 = tileY * 16;            // unit base
    const int ks = warp % KS;
    const int rem = warp / KS;
    const int wn = rem & 1;               // 0..1 (32-col slices)
    const int wm = rem >> 1;              // 0..WM-1 (32-row slices)

    if (tid < 64)
        *reinterpret_cast<float*>(smem + OFF_BIAS + tid * 4) = biasr[n0 + tid];

    float cfr[2][4][4];   // hi*hi
    float cfl[2][4][4];   // hi*lo + lo*hi
#pragma unroll
    for (int mi = 0; mi < 2; mi++)
#pragma unroll
        for (int nj = 0; nj < 4; nj++)
#pragma unroll
            for (int r = 0; r < 4; r++) { cfr[mi][nj][r] = 0.f; cfl[mi][nj][r] = 0.f; }

    const int NC = 8 + ncx;

    auto prefetch = [&](int ch) {
        const __nv_bfloat16 *aH, *aL, *bH, *bL;
        int lda, k0;
        if (ch < 8) { aH = AhH; aL = AhL; bH = BhH; bL = BhL; lda = HID; k0 = ch * 64; }
        else        { aH = AxH; aL = AxL; bH = BxH; bL = BxL; lda = ldx; k0 = (ch - 8) * 64; }
        const uint32_t st = sbase + (ch % NSTAGE) * STAGE;
        // A: MT rows x 64 bf16 (MT*8 16B chunks), hi + lo
#pragma unroll
        for (int i = 0; i < (MT * 8) / NTHREADS; i++) {
            int idx = tid + i * NTHREADS;
            int r = idx >> 3, q = idx & 7;
            uint32_t off = r * ROW_B + q * 16;
            long ao = (long)(m0 + r) * lda + k0 + q * 8;
            CP_ASYNC16(st + OFF_AH + off, aH + ao);
            CP_ASYNC16(st + OFF_AL + off, aL + ao);
        }
        // B: 64 rows x 64 bf16 (512 16B chunks), hi + lo
        {
            int r = tid >> 3, q = tid & 7;
            uint32_t off = r * ROW_B + q * 16;
            long bo = (long)(n0 + r) * lda + k0 + q * 8;
            CP_ASYNC16(st + OFF_BH + off, bH + bo);
            CP_ASYNC16(st + OFF_BL + off, bL + bo);
        }
    };

    prefetch(0); CP_COMMIT();
    prefetch(1); CP_COMMIT();

    for (int ch = 0; ch < NC; ch++) {
        if (ch + 1 < NC) CP_WAIT1(); else CP_WAIT0();
        __syncthreads();                    // publishes chunk ch
        if (ch + 2 < NC) { prefetch(ch + 2); CP_COMMIT(); }

        const uint32_t base = sbase + (ch % NSTAGE) * STAGE;
#pragma unroll
        for (int ki = 0; ki < KITER; ki++) {
            const int kk = (ks * KITER + ki) * 16;
            uint32_t ah[2][4], al[2][4], bh[4][2], bl[4][2];
#pragma unroll
            for (int mi = 0; mi < 2; mi++) {
                uint32_t roff =
                    (uint32_t)((wm * 32 + mi * 16 + (lane & 15)) * ROW_B +
                               (kk + (lane >> 4) * 8) * 2);
                LDM4(ah[mi], base + OFF_AH + roff);
                LDM4(al[mi], base + OFF_AL + roff);
            }
#pragma unroll
            for (int p = 0; p < 2; p++) {
                uint32_t roff =
                    (uint32_t)((wn * 32 + p * 16 + (lane & 15)) * ROW_B +
                               (kk + (lane >> 4) * 8) * 2);
                uint32_t rb[4], rl[4];
                LDM4(rb, base + OFF_BH + roff);
                LDM4(rl, base + OFF_BL + roff);
                bh[p * 2 + 0][0] = rb[0]; bh[p * 2 + 0][1] = rb[2];
                bh[p * 2 + 1][0] = rb[1]; bh[p * 2 + 1][1] = rb[3];
                bl[p * 2 + 0][0] = rl[0]; bl[p * 2 + 0][1] = rl[2];
                bl[p * 2 + 1][0] = rl[1]; bl[p * 2 + 1][1] = rl[3];
            }
#pragma unroll
            for (int mi = 0; mi < 2; mi++)
#pragma unroll
                for (int nj = 0; nj < 4; nj++) {
                    MMA16816(cfr[mi][nj], ah[mi], bh[nj][0], bh[nj][1]);
                    MMA16816(cfl[mi][nj], ah[mi], bl[nj][0], bl[nj][1]);
                    MMA16816(cfl[mi][nj], al[mi], bh[nj][0], bh[nj][1]);
                }
        }
    }
    __syncthreads();   // all ldmatrix reads done before Cs overwrites stage 0

    // ---- epilogue: K-group phased reduction into smem C tile ----
    float* Cs = reinterpret_cast<float*>(smem);   // MT x CS_STRIDE fp32
#pragma unroll
    for (int g = 0; g < KS; g++) {
        if (ks == g) {
#pragma unroll
            for (int mi = 0; mi < 2; mi++)
#pragma unroll
                for (int nj = 0; nj < 4; nj++) {
                    int r = wm * 32 + mi * 16 + (lane >> 2);
                    int col = wn * 32 + nj * 8 + (lane & 3) * 2;
                    float v0 = cfr[mi][nj][0] + cfl[mi][nj][0];
                    float v1 = cfr[mi][nj][1] + cfl[mi][nj][1];
                    float v2 = cfr[mi][nj][2] + cfl[mi][nj][2];
                    float v3 = cfr[mi][nj][3] + cfl[mi][nj][3];
                    if (g == 0) {
                        Cs[r * CS_STRIDE + col]           = v0;
                        Cs[r * CS_STRIDE + col + 1]       = v1;
                        Cs[(r + 8) * CS_STRIDE + col]     = v2;
                        Cs[(r + 8) * CS_STRIDE + col + 1] = v3;
                    } else {
                        Cs[r * CS_STRIDE + col]           += v0;
                        Cs[r * CS_STRIDE + col + 1]       += v1;
                        Cs[(r + 8) * CS_STRIDE + col]     += v2;
                        Cs[(r + 8) * CS_STRIDE + col + 1] += v3;
                    }
                }
        }
        __syncthreads();
    }

    const float* Bs = reinterpret_cast<const float*>(smem + OFF_BIAS);
#pragma unroll
    for (int k = 0; k < (MT * 16) / NTHREADS; k++) {
        int id = tid + k * NTHREADS;
        int u = id & 15, bb = id >> 4;        // bb 0..MT-1
        float4 g4 = *reinterpret_cast<const float4*>(&Cs[bb * CS_STRIDE + u * 4]);
        float gi = sigmoidf_(g4.x + Bs[u * 4 + 0]);
        float gf = sigmoidf_(g4.y + Bs[u * 4 + 1]);
        float gg = tanhf_   (g4.z + Bs[u * 4 + 2]);
        float go = sigmoidf_(g4.w + Bs[u * 4 + 3]);
        int gidx = (m0 + bb) * HID + u0 + u;
        float cn = gf * c[gidx] + gi * gg;
        c[gidx] = cn;
        float hv = go * tanhf_(cn);
        hf[gidx] = hv;
        __nv_bfloat16 hh, ll; split2(hv, hh, ll);
        hhi[gidx] = hh; hlo[gidx] = ll;
    }
}

// ---------------------------------------------------------------------------
// Single-cell kernel (decoder + encoder endpoints): MT=64, KS=4, grid (4,32)
// ---------------------------------------------------------------------------
__global__ void __launch_bounds__(NTHREADS, 1)
cell_mma(const __nv_bfloat16* __restrict__ AhH, const __nv_bfloat16* __restrict__ AhL,
         const __nv_bfloat16* __restrict__ BhH, const __nv_bfloat16* __restrict__ BhL,
         const __nv_bfloat16* __restrict__ AxH, const __nv_bfloat16* __restrict__ AxL,
         const __nv_bfloat16* __restrict__ BxH, const __nv_bfloat16* __restrict__ BxL,
         int ncx, int ldx,
         const float* __restrict__ biasr,
         float* __restrict__ c, float* __restrict__ hf,
         __nv_bfloat16* __restrict__ hhi, __nv_bfloat16* __restrict__ hlo) {
    extern __shared__ __align__(16) char smem[];
    cell_body<64, 4>(smem, blockIdx.x * 64, blockIdx.y,
                     AhH, AhL, BhH, BhL, AxH, AxL, BxH, BxL,
                     ncx, ldx, biasr, c, hf, hhi, hlo);
}

// ---------------------------------------------------------------------------
// Merged encoder wavefront step: MT=128, KS=2, grid (2,64) = 128 CTAs/1 wave.
// L1(t) on tiles y<32, L0(t+1) on tiles y>=32.
// ---------------------------------------------------------------------------
__global__ void __launch_bounds__(NTHREADS, 1)
enc_step(// L1(t):
         const __nv_bfloat16* __restrict__ h1pH, const __nv_bfloat16* __restrict__ h1pL,
         const __nv_bfloat16* __restrict__ w1hhh, const __nv_bfloat16* __restrict__ w1hhl,
         const __nv_bfloat16* __restrict__ y0tH, const __nv_bfloat16* __restrict__ y0tL,
         const __nv_bfloat16* __restrict__ w1ihh, const __nv_bfloat16* __restrict__ w1ihl,
         const float* __restrict__ br1, float* __restrict__ c1,
         float* __restrict__ h1f,
         __nv_bfloat16* __restrict__ h1oh, __nv_bfloat16* __restrict__ h1ol,
         // L0(t+1):
         const __nv_bfloat16* __restrict__ xnH, const __nv_bfloat16* __restrict__ xnL,
         const __nv_bfloat16* __restrict__ w0h, const __nv_bfloat16* __restrict__ w0l,
         const __nv_bfloat16* __restrict__ wx0h, const __nv_bfloat16* __restrict__ wx0l,
         const float* __restrict__ br0, float* __restrict__ c0,
         float* __restrict__ h0f,
         __nv_bfloat16* __restrict__ y0nH, __nv_bfloat16* __restrict__ y0nL) {
    extern __shared__ __align__(16) char smem[];
    const int m0 = blockIdx.x * 128;
    if (blockIdx.y < 32) {
        cell_body<128, 2>(smem, m0, blockIdx.y,
                          h1pH, h1pL, w1hhh, w1hhl, y0tH, y0tL, w1ihh, w1ihl,
                          8, HID, br1, c1, h1f, h1oh, h1ol);
    } else {
        cell_body<128, 2>(smem, m0, blockIdx.y - 32,
                          y0tH, y0tL, w0h, w0l, xnH, xnL, wx0h, wx0l,
                          1, XPW, br0, c0, h0f, y0nH, y0nL);
    }
}

// ---------------------------------------------------------------------------
// head: pred += h1 @ headW^T + headb ; write output[t]; build next decoder x
// ---------------------------------------------------------------------------
__global__ void head_kernel(const float* __restrict__ h1,
                            const float* __restrict__ headW,
                            const float* __restrict__ headb,
                            float* __restrict__ pred,
                            float* __restrict__ out_t,
                            const float* __restrict__ wf_next,
                            __nv_bfloat16* __restrict__ xdh,
                            __nv_bfloat16* __restrict__ xdl) {
    int b = blockIdx.x;
    int w = threadIdx.x >> 5;
    int lane = threadIdx.x & 31;
    const float* hr = &h1[b * HID];
    const float* wr = &headW[w * HID];
    float s = 0.f;
    for (int k = lane; k < HID; k += 32) s += hr[k] * wr[k];
#pragma unroll
    for (int o = 16; o; o >>= 1) s += __shfl_down_sync(0xffffffffu, s, o);
    if (lane == 0) {
        float p = pred[b * VEG + w] + s + headb[w];
        pred[b * VEG + w] = p;
        out_t[b * (T_FUT * VEG) + w] = p;
        __nv_bfloat16 hh, ll; split2(p, hh, ll);
        xdh[b * XPW + w] = hh; xdl[b * XPW + w] = ll;
    }
    if (threadIdx.x < WEA && wf_next) {
        float v = wf_next[b * (T_FUT * WEA) + threadIdx.x];
        __nv_bfloat16 hh, ll; split2(v, hh, ll);
        xdh[b * XPW + VEG + threadIdx.x] = hh;
        xdl[b * XPW + VEG + threadIdx.x] = ll;
    }
}

// ---------------------------------------------------------------------------
// Host launcher (single stream — graph-capture safe)
// ---------------------------------------------------------------------------
extern "C" void kernel_launch(void* const* d_in, const int* in_sizes, int n_in,
                              void* d_out, int out_size) {
    const float* veg   = (const float*)d_in[0];
    const float* wh    = (const float*)d_in[1];
    const float* wf    = (const float*)d_in[2];
    const float* Wih0  = (const float*)d_in[3];
    const float* Whh0  = (const float*)d_in[4];
    const float* b0    = (const float*)d_in[5];
    const float* Wih1  = (const float*)d_in[6];
    const float* Whh1  = (const float*)d_in[7];
    const float* b1    = (const float*)d_in[8];
    const float* headW = (const float*)d_in[9];
    const float* headb = (const float*)d_in[10];
    float* out = (float*)d_out;

    __nv_bfloat16 *xph, *xpl, *xdh, *xdl, *y0h, *y0l, *zb;
    __nv_bfloat16 *h1h, *h1l, *h0h, *h0l;
    __nv_bfloat16 *w0h, *w0l, *w1hhh, *w1hhl, *w1ihh, *w1ihl, *wx0h, *wx0l;
    float *pred, *c0, *c1, *h1f, *h0f, *br0, *br1;
    cudaGetSymbolAddress((void**)&xph,   g_xph);
    cudaGetSymbolAddress((void**)&xpl,   g_xpl);
    cudaGetSymbolAddress((void**)&xdh,   g_xdh);
    cudaGetSymbolAddress((void**)&xdl,   g_xdl);
    cudaGetSymbolAddress((void**)&pred,  g_pred);
    cudaGetSymbolAddress((void**)&y0h,   g_y0h);
    cudaGetSymbolAddress((void**)&y0l,   g_y0l);
    cudaGetSymbolAddress((void**)&zb,    g_zb);
    cudaGetSymbolAddress((void**)&c0,    g_c0);
    cudaGetSymbolAddress((void**)&c1,    g_c1);
    cudaGetSymbolAddress((void**)&h1h,   g_h1h);
    cudaGetSymbolAddress((void**)&h1l,   g_h1l);
    cudaGetSymbolAddress((void**)&h0h,   g_h0h);
    cudaGetSymbolAddress((void**)&h0l,   g_h0l);
    cudaGetSymbolAddress((void**)&h1f,   g_h1f);
    cudaGetSymbolAddress((void**)&h0f,   g_h0f);
    cudaGetSymbolAddress((void**)&w0h,   g_w0h);
    cudaGetSymbolAddress((void**)&w0l,   g_w0l);
    cudaGetSymbolAddress((void**)&w1hhh, g_w1hh_h);
    cudaGetSymbolAddress((void**)&w1hhl, g_w1hh_l);
    cudaGetSymbolAddress((void**)&w1ihh, g_w1ih_h);
    cudaGetSymbolAddress((void**)&w1ihl, g_w1ih_l);
    cudaGetSymbolAddress((void**)&wx0h,  g_wx0h);
    cudaGetSymbolAddress((void**)&wx0l,  g_wx0l);
    cudaGetSymbolAddress((void**)&br0,   g_br0);
    cudaGetSymbolAddress((void**)&br1,   g_br1);

    cudaFuncSetAttribute(cell_mma, cudaFuncAttributeMaxDynamicSharedMemorySize,
                         SMEM_TOTAL_(64));
    cudaFuncSetAttribute(enc_step, cudaFuncAttributeMaxDynamicSharedMemorySize,
                         SMEM_TOTAL_(128));

    dim3 grid1(4, 32), grid2(2, 64), blk(NTHREADS);

    prep_kernel<<<T_HIST, NB>>>(veg, wh, wf, xph, xpl, xdh, xdl, pred);
    wprep_kernel<<<GROW, 128>>>(Wih0, Whh0, b0, Wih1, Whh1, b1,
                                w0h, w0l, w1hhh, w1hhl, w1ihh, w1ihl,
                                wx0h, wx0l, br0, br1);
    zero_kernel<<<(HB + 255) / 256, 256>>>(c0, c1, zb);

    // L0(0) alone
    cell_mma<<<grid1, blk, SMEM_TOTAL_(64)>>>(
        zb, zb, w0h, w0l, xph, xpl, wx0h, wx0l,
        1, XPW, br0, c0, h0f, y0h, y0l);

    // merged wavefront: t = 0..148 computes L1(t) and L0(t+1) concurrently
    for (int t = 0; t < T_HIST - 1; t++) {
        const __nv_bfloat16* h1pH = (t == 0) ? zb : (h1h + ((t + 1) & 1) * HB);
        const __nv_bfloat16* h1pL = (t == 0) ? zb : (h1l + ((t + 1) & 1) * HB);
        enc_step<<<grid2, blk, SMEM_TOTAL_(128)>>>(
            h1pH, h1pL, w1hhh, w1hhl,
            y0h + (size_t)t * HB, y0l + (size_t)t * HB, w1ihh, w1ihl,
            br1, c1, h1f, h1h + (t & 1) * HB, h1l + (t & 1) * HB,
            xph + (size_t)(t + 1) * NB * XPW, xpl + (size_t)(t + 1) * NB * XPW,
            w0h, w0l, wx0h, wx0l,
            br0, c0, h0f,
            y0h + (size_t)(t + 1) * HB, y0l + (size_t)(t + 1) * HB);
    }
    // final L1(149): reads h1[148&1=0], writes h1[149&1=1]
    {
        int t = T_HIST - 1;
        cell_mma<<<grid1, blk, SMEM_TOTAL_(64)>>>(
            h1h + ((t + 1) & 1) * HB, h1l + ((t + 1) & 1) * HB, w1hhh, w1hhl,
            y0h + (size_t)t * HB, y0l + (size_t)t * HB, w1ihh, w1ihl,
            8, HID, br1, c1, h1f, h1h + (t & 1) * HB, h1l + (t & 1) * HB);
    }

    // decoder (serial dependence); h1 phases: read (t+1)&1, write t&1
    for (int t = 0; t < T_FUT; t++) {
        const __nv_bfloat16* hpH = (t == 0) ? (y0h + (size_t)(T_HIST - 1) * HB)
                                            : (h0h + ((t + 1) & 1) * HB);
        const __nv_bfloat16* hpL = (t == 0) ? (y0l + (size_t)(T_HIST - 1) * HB)
                                            : (h0l + ((t + 1) & 1) * HB);
        cell_mma<<<grid1, blk, SMEM_TOTAL_(64)>>>(
            hpH, hpL, w0h, w0l, xdh, xdl, wx0h, wx0l,
            1, XPW, br0, c0, h0f, h0h + (t & 1) * HB, h0l + (t & 1) * HB);
        cell_mma<<<grid1, blk, SMEM_TOTAL_(64)>>>(
            h1h + ((t + 1) & 1) * HB, h1l + ((t + 1) & 1) * HB, w1hhh, w1hhl,
            h0h + (t & 1) * HB, h0l + (t & 1) * HB, w1ihh, w1ihl,
            8, HID, br1, c1, h1f, h1h + (t & 1) * HB, h1l + (t & 1) * HB);
        const float* wfn = (t < T_FUT - 1) ? (wf + (t + 1) * WEA) : nullptr;
        head_kernel<<<NB, 128>>>(h1f, headW, headb, pred,
                                 out + t * VEG, wfn, xdh, xdl);
    }
}

// round 10
// speedup vs baseline: 1.3630x; 1.1474x over previous
#include <cuda_runtime.h>
#include <cuda_bf16.h>
#include <cstdint>
#include <math.h>

// ---------------------------------------------------------------------------
// Problem constants
// ---------------------------------------------------------------------------
#define VEG 4
#define WEA 8
#define HID 512
#define NB  256
#define T_HIST 150
#define T_FUT  50
#define HB (NB * HID)
#define XPW 64            // padded x width (12 real + 52 zeros)
#define GROW 2048         // gate rows (4*HID)
#define NTHREADS 256      // 8 warps per CTA, occupancy 2

// ---------------------------------------------------------------------------
// Device scratch (static only)
// ---------------------------------------------------------------------------
__device__ __nv_bfloat16 g_xph[T_HIST * NB * XPW];
__device__ __nv_bfloat16 g_xpl[T_HIST * NB * XPW];
__device__ __nv_bfloat16 g_xdh[NB * XPW];
__device__ __nv_bfloat16 g_xdl[NB * XPW];
__device__ float g_pred[NB * VEG];
__device__ __nv_bfloat16 g_y0h[T_HIST * HB];   // layer0 outputs hi (h-chain)
__device__ __nv_bfloat16 g_y0l[T_HIST * HB];
__device__ __nv_bfloat16 g_zb[HB];             // bf16 zeros
__device__ float g_c0[HB];
__device__ float g_c1[HB];
__device__ __nv_bfloat16 g_h1h[2 * HB], g_h1l[2 * HB];
__device__ __nv_bfloat16 g_h0h[2 * HB], g_h0l[2 * HB];
__device__ float g_h1f[HB];
__device__ float g_h0f[HB];                    // sink for layer0 fp32 h
// reordered (row = u*4+g) hi/lo weights
__device__ __nv_bfloat16 g_w0h[GROW * HID], g_w0l[GROW * HID];        // Whh0
__device__ __nv_bfloat16 g_w1hh_h[GROW * HID], g_w1hh_l[GROW * HID];  // Whh1
__device__ __nv_bfloat16 g_w1ih_h[GROW * HID], g_w1ih_l[GROW * HID];  // Wih1
__device__ __nv_bfloat16 g_wx0h[GROW * XPW], g_wx0l[GROW * XPW];      // Wih0 padded
__device__ float g_br0[GROW], g_br1[GROW];

// ---------------------------------------------------------------------------
// Portable PTX helpers (sm_80+ only)
// ---------------------------------------------------------------------------
__device__ __forceinline__ uint32_t smem_u32(const void* p) {
    uint32_t a;
    asm("{ .reg .u64 t; cvta.to.shared.u64 t, %1; cvt.u32.u64 %0, t; }"
        : "=r"(a) : "l"(p));
    return a;
}
#define CP_ASYNC16(dst, src) \
    asm volatile("cp.async.cg.shared.global [%0], [%1], 16;" \
                 :: "r"(dst), "l"(src) : "memory")
#define CP_COMMIT() asm volatile("cp.async.commit_group;" ::: "memory")
#define CP_WAIT1()  asm volatile("cp.async.wait_group 1;" ::: "memory")
#define CP_WAIT0()  asm volatile("cp.async.wait_group 0;" ::: "memory")

#define LDM4(r, addr) \
    asm volatile("ldmatrix.sync.aligned.m8n8.x4.shared.b16 {%0,%1,%2,%3}, [%4];" \
                 : "=r"((r)[0]), "=r"((r)[1]), "=r"((r)[2]), "=r"((r)[3]) \
                 : "r"(addr))

#define MMA16816(d, a, b0, b1) \
    asm volatile( \
        "mma.sync.aligned.m16n8k16.row.col.f32.bf16.bf16.f32 " \
        "{%0,%1,%2,%3}, {%4,%5,%6,%7}, {%8,%9}, {%0,%1,%2,%3};" \
        : "+f"((d)[0]), "+f"((d)[1]), "+f"((d)[2]), "+f"((d)[3]) \
        : "r"((a)[0]), "r"((a)[1]), "r"((a)[2]), "r"((a)[3]), \
          "r"(b0), "r"(b1))

// ---------------------------------------------------------------------------
// SMEM layout (parameterized by M tile)
// ---------------------------------------------------------------------------
#define SM_STRIDE 72                        // bf16 elems/row (144B, conflict-free)
#define ROW_B (SM_STRIDE * 2)               // 144 bytes
#define B_TILE_BYTES (64 * ROW_B)           // 9216
#define NSTAGE 3
#define CS_STRIDE 68                        // fp32 C tile row stride

#define A_TILE_BYTES_(MT) ((MT) * ROW_B)
#define STAGE_BYTES_(MT)  (2 * A_TILE_BYTES_(MT) + 2 * B_TILE_BYTES)
#define OFF_BIAS_(MT)     (NSTAGE * STAGE_BYTES_(MT))
#define SMEM_TOTAL_(MT)   (OFF_BIAS_(MT) + 64 * 4 + 16)
// MT=32: stage 27648, total 83216  (2/SM = 166KB)
// MT=64: stage 36864, total 110864 (2/SM = 221.7KB)

// ---------------------------------------------------------------------------
// Math helpers
// ---------------------------------------------------------------------------
__device__ __forceinline__ float sigmoidf_(float x) { return 1.0f / (1.0f + __expf(-x)); }
__device__ __forceinline__ float tanhf_(float x)    { return 2.0f / (1.0f + __expf(-2.0f * x)) - 1.0f; }
__device__ __forceinline__ void split2(float x, __nv_bfloat16& h, __nv_bfloat16& l) {
    h = __float2bfloat16(x);
    l = __float2bfloat16(x - __bfloat162float(h));
}

// ---------------------------------------------------------------------------
// prep: smoothing + padded-x hi/lo for encoder; decoder init at t=149
// ---------------------------------------------------------------------------
__global__ void prep_kernel(const float* __restrict__ veg,
                            const float* __restrict__ wh,
                            const float* __restrict__ wf,
                            __nv_bfloat16* __restrict__ xph,
                            __nv_bfloat16* __restrict__ xpl,
                            __nv_bfloat16* __restrict__ xdh,
                            __nv_bfloat16* __restrict__ xdl,
                            float* __restrict__ pred) {
    int b = threadIdx.x;
    int t = blockIdx.x;
    const int base = (t * NB + b) * XPW;
    float vs[VEG];
#pragma unroll
    for (int v = 0; v < VEG; v++) {
        float val = veg[b * (T_HIST * VEG) + t * VEG + v];
        float s = 0.f;
#pragma unroll
        for (int dt = -2; dt <= 2; dt++) {
            int tt = t + dt;
            if (tt >= 0 && tt < T_HIST) {
                float u = veg[b * (T_HIST * VEG) + tt * VEG + v];
                if (!isnan(u)) s += u;
            }
        }
        float sm = s * 0.2f;
        float outv = isnan(val) ? sm : val;
        if (isnan(outv)) outv = 0.f;
        vs[v] = outv;
        __nv_bfloat16 hh, ll; split2(outv, hh, ll);
        xph[base + v] = hh; xpl[base + v] = ll;
    }
#pragma unroll
    for (int k = 0; k < WEA; k++) {
        float w = wh[b * (T_HIST * WEA) + t * WEA + k];
        __nv_bfloat16 hh, ll; split2(w, hh, ll);
        xph[base + VEG + k] = hh; xpl[base + VEG + k] = ll;
    }
    __nv_bfloat16 z = __float2bfloat16(0.f);
    for (int c = VEG + WEA; c < XPW; c++) { xph[base + c] = z; xpl[base + c] = z; }

    if (t == T_HIST - 1) {
        int db = b * XPW;
#pragma unroll
        for (int v = 0; v < VEG; v++) {
            pred[b * VEG + v] = vs[v];
            __nv_bfloat16 hh, ll; split2(vs[v], hh, ll);
            xdh[db + v] = hh; xdl[db + v] = ll;
        }
#pragma unroll
        for (int k = 0; k < WEA; k++) {
            float w = wf[b * (T_FUT * WEA) + k];
            __nv_bfloat16 hh, ll; split2(w, hh, ll);
            xdh[db + VEG + k] = hh; xdl[db + VEG + k] = ll;
        }
        for (int c = VEG + WEA; c < XPW; c++) { xdh[db + c] = z; xdl[db + c] = z; }
    }
}

// ---------------------------------------------------------------------------
// weight prep: reorder rows to u*4+g, split hi/lo, pad Wih0 to 64 cols
// ---------------------------------------------------------------------------
__global__ void wprep_kernel(const float* __restrict__ Wih0, const float* __restrict__ Whh0,
                             const float* __restrict__ b0,   const float* __restrict__ Wih1,
                             const float* __restrict__ Whh1, const float* __restrict__ b1,
                             __nv_bfloat16* w0h, __nv_bfloat16* w0l,
                             __nv_bfloat16* w1hhh, __nv_bfloat16* w1hhl,
                             __nv_bfloat16* w1ihh, __nv_bfloat16* w1ihl,
                             __nv_bfloat16* wx0h, __nv_bfloat16* wx0l,
                             float* br0, float* br1) {
    int rn = blockIdx.x;                       // new row
    int orig = (rn & 3) * HID + (rn >> 2);     // g*512 + u
    for (int c = threadIdx.x; c < HID; c += blockDim.x) {
        __nv_bfloat16 hh, ll;
        split2(Whh0[orig * HID + c], hh, ll);
        w0h[rn * HID + c] = hh; w0l[rn * HID + c] = ll;
        split2(Whh1[orig * HID + c], hh, ll);
        w1hhh[rn * HID + c] = hh; w1hhl[rn * HID + c] = ll;
        split2(Wih1[orig * HID + c], hh, ll);
        w1ihh[rn * HID + c] = hh; w1ihl[rn * HID + c] = ll;
    }
    if (threadIdx.x < XPW) {
        int c = threadIdx.x;
        float v = (c < VEG + WEA) ? Wih0[orig * (VEG + WEA) + c] : 0.f;
        __nv_bfloat16 hh, ll; split2(v, hh, ll);
        wx0h[rn * XPW + c] = hh; wx0l[rn * XPW + c] = ll;
    }
    if (threadIdx.x == 0) { br0[rn] = b0[orig]; br1[rn] = b1[orig]; }
}

__global__ void zero_kernel(float* __restrict__ c0, float* __restrict__ c1,
                            __nv_bfloat16* __restrict__ zb) {
    int i = blockIdx.x * blockDim.x + threadIdx.x;
    if (i < HB) { c0[i] = 0.f; c1[i] = 0.f; zb[i] = __float2bfloat16(0.f); }
}

// ---------------------------------------------------------------------------
// Cell body: one MT(batch)x64(gate) tile of a fused LSTM step on HMMA.
// 8 warps: (MT/32) M x 2 N x KS K-groups, warp tile 32x32 (KS = 4/(MT/32)*... :
//   MT=32 -> KS=4 (KITER=1), MT=64 -> KS=2 (KITER=2)).
// K-group partial sums go to separate smem slabs, summed in the epilogue.
// ---------------------------------------------------------------------------
template <int MT>
__device__ __forceinline__ void cell_body(
    char* smem, int m0, int tileY,
    const __nv_bfloat16* __restrict__ AhH, const __nv_bfloat16* __restrict__ AhL,
    const __nv_bfloat16* __restrict__ BhH, const __nv_bfloat16* __restrict__ BhL,
    const __nv_bfloat16* __restrict__ AxH, const __nv_bfloat16* __restrict__ AxL,
    const __nv_bfloat16* __restrict__ BxH, const __nv_bfloat16* __restrict__ BxL,
    int ncx, int ldx,
    const float* __restrict__ biasr,
    float* __restrict__ c, float* __restrict__ hf,
    __nv_bfloat16* __restrict__ hhi, __nv_bfloat16* __restrict__ hlo) {

    constexpr int A_TILE = A_TILE_BYTES_(MT);
    constexpr int STAGE  = STAGE_BYTES_(MT);
    constexpr int OFF_AH = 0;
    constexpr int OFF_AL = A_TILE;
    constexpr int OFF_BH = 2 * A_TILE;
    constexpr int OFF_BL = 2 * A_TILE + B_TILE_BYTES;
    constexpr int OFF_BIAS = OFF_BIAS_(MT);
    constexpr int WM = MT / 32;           // M warp-slices (1 or 2)
    constexpr int KS = 8 / (WM * 2);      // K-groups (4 or 2)
    constexpr int KITER = 4 / KS;         // kk slices per warp per chunk
    constexpr int CSLAB = MT * CS_STRIDE; // floats per K-group C slab
    static_assert(WM * 2 * KS == 8, "warp layout");

    const uint32_t sbase = smem_u32(smem);
    const int tid = threadIdx.x;
    const int warp = tid >> 5;
    const int lane = tid & 31;
    const int n0 = tileY * 64;            // reordered weight row base
    const int u0 = tileY * 16;            // unit base
    const int ks = warp % KS;
    const int rem = warp / KS;
    const int wn = rem & 1;               // 0..1 (32-col slices)
    const int wm = rem >> 1;              // 0..WM-1 (32-row slices)

    if (tid < 64)
        *reinterpret_cast<float*>(smem + OFF_BIAS + tid * 4) = biasr[n0 + tid];

    float cfr[2][4][4];   // hi*hi
    float cfl[2][4][4];   // hi*lo + lo*hi
#pragma unroll
    for (int mi = 0; mi < 2; mi++)
#pragma unroll
        for (int nj = 0; nj < 4; nj++)
#pragma unroll
            for (int r = 0; r < 4; r++) { cfr[mi][nj][r] = 0.f; cfl[mi][nj][r] = 0.f; }

    const int NC = 8 + ncx;

    auto prefetch = [&](int ch) {
        const __nv_bfloat16 *aH, *aL, *bH, *bL;
        int lda, k0;
        if (ch < 8) { aH = AhH; aL = AhL; bH = BhH; bL = BhL; lda = HID; k0 = ch * 64; }
        else        { aH = AxH; aL = AxL; bH = BxH; bL = BxL; lda = ldx; k0 = (ch - 8) * 64; }
        const uint32_t st = sbase + (ch % NSTAGE) * STAGE;
        // A: MT rows x 64 bf16 (MT*8 16B chunks), hi + lo
#pragma unroll
        for (int i = 0; i < (MT * 8) / NTHREADS; i++) {
            int idx = tid + i * NTHREADS;
            int r = idx >> 3, q = idx & 7;
            uint32_t off = r * ROW_B + q * 16;
            long ao = (long)(m0 + r) * lda + k0 + q * 8;
            CP_ASYNC16(st + OFF_AH + off, aH + ao);
            CP_ASYNC16(st + OFF_AL + off, aL + ao);
        }
        // B: 64 rows x 64 bf16 (512 16B chunks), hi + lo
#pragma unroll
        for (int i = 0; i < 512 / NTHREADS; i++) {
            int idx = tid + i * NTHREADS;
            int r = idx >> 3, q = idx & 7;
            uint32_t off = r * ROW_B + q * 16;
            long bo = (long)(n0 + r) * lda + k0 + q * 8;
            CP_ASYNC16(st + OFF_BH + off, bH + bo);
            CP_ASYNC16(st + OFF_BL + off, bL + bo);
        }
    };

    prefetch(0); CP_COMMIT();
    prefetch(1); CP_COMMIT();

    for (int ch = 0; ch < NC; ch++) {
        if (ch + 1 < NC) CP_WAIT1(); else CP_WAIT0();
        __syncthreads();                    // publishes chunk ch
        if (ch + 2 < NC) { prefetch(ch + 2); CP_COMMIT(); }

        const uint32_t base = sbase + (ch % NSTAGE) * STAGE;
#pragma unroll
        for (int ki = 0; ki < KITER; ki++) {
            const int kk = (ks * KITER + ki) * 16;
            uint32_t ah[2][4], al[2][4], bh[4][2], bl[4][2];
#pragma unroll
            for (int mi = 0; mi < 2; mi++) {
                uint32_t roff =
                    (uint32_t)((wm * 32 + mi * 16 + (lane & 15)) * ROW_B +
                               (kk + (lane >> 4) * 8) * 2);
                LDM4(ah[mi], base + OFF_AH + roff);
                LDM4(al[mi], base + OFF_AL + roff);
            }
#pragma unroll
            for (int p = 0; p < 2; p++) {
                uint32_t roff =
                    (uint32_t)((wn * 32 + p * 16 + (lane & 15)) * ROW_B +
                               (kk + (lane >> 4) * 8) * 2);
                uint32_t rb[4], rl[4];
                LDM4(rb, base + OFF_BH + roff);
                LDM4(rl, base + OFF_BL + roff);
                bh[p * 2 + 0][0] = rb[0]; bh[p * 2 + 0][1] = rb[2];
                bh[p * 2 + 1][0] = rb[1]; bh[p * 2 + 1][1] = rb[3];
                bl[p * 2 + 0][0] = rl[0]; bl[p * 2 + 0][1] = rl[2];
                bl[p * 2 + 1][0] = rl[1]; bl[p * 2 + 1][1] = rl[3];
            }
#pragma unroll
            for (int mi = 0; mi < 2; mi++)
#pragma unroll
                for (int nj = 0; nj < 4; nj++) {
                    MMA16816(cfr[mi][nj], ah[mi], bh[nj][0], bh[nj][1]);
                    MMA16816(cfl[mi][nj], ah[mi], bl[nj][0], bl[nj][1]);
                    MMA16816(cfl[mi][nj], al[mi], bh[nj][0], bh[nj][1]);
                }
        }
    }
    __syncthreads();   // all ldmatrix reads done before Cs overwrites stage 0

    // ---- epilogue: per-K-group C slabs (no phased barriers) ----
    float* Cs = reinterpret_cast<float*>(smem);   // KS slabs of MT x CS_STRIDE
    {
        float* Cg = Cs + ks * CSLAB;
#pragma unroll
        for (int mi = 0; mi < 2; mi++)
#pragma unroll
            for (int nj = 0; nj < 4; nj++) {
                int r = wm * 32 + mi * 16 + (lane >> 2);
                int col = wn * 32 + nj * 8 + (lane & 3) * 2;
                Cg[r * CS_STRIDE + col]           = cfr[mi][nj][0] + cfl[mi][nj][0];
                Cg[r * CS_STRIDE + col + 1]       = cfr[mi][nj][1] + cfl[mi][nj][1];
                Cg[(r + 8) * CS_STRIDE + col]     = cfr[mi][nj][2] + cfl[mi][nj][2];
                Cg[(r + 8) * CS_STRIDE + col + 1] = cfr[mi][nj][3] + cfl[mi][nj][3];
            }
    }
    __syncthreads();

    const float* Bs = reinterpret_cast<const float*>(smem + OFF_BIAS);
#pragma unroll
    for (int k = 0; k < (MT * 16) / NTHREADS; k++) {
        int id = tid + k * NTHREADS;
        int u = id & 15, bb = id >> 4;        // bb 0..MT-1
        float4 g4 = *reinterpret_cast<const float4*>(&Cs[bb * CS_STRIDE + u * 4]);
#pragma unroll
        for (int g = 1; g < KS; g++) {
            float4 p4 = *reinterpret_cast<const float4*>(
                &Cs[g * CSLAB + bb * CS_STRIDE + u * 4]);
            g4.x += p4.x; g4.y += p4.y; g4.z += p4.z; g4.w += p4.w;
        }
        float gi = sigmoidf_(g4.x + Bs[u * 4 + 0]);
        float gf = sigmoidf_(g4.y + Bs[u * 4 + 1]);
        float gg = tanhf_   (g4.z + Bs[u * 4 + 2]);
        float go = sigmoidf_(g4.w + Bs[u * 4 + 3]);
        int gidx = (m0 + bb) * HID + u0 + u;
        float cn = gf * c[gidx] + gi * gg;
        c[gidx] = cn;
        float hv = go * tanhf_(cn);
        hf[gidx] = hv;
        __nv_bfloat16 hh, ll; split2(hv, hh, ll);
        hhi[gidx] = hh; hlo[gidx] = ll;
    }
}

// ---------------------------------------------------------------------------
// Single-cell kernel (decoder + encoder endpoints): MT=32, grid (8,32)=256
// CTAs, 2 CTAs/SM fully resident.
// ---------------------------------------------------------------------------
__global__ void __launch_bounds__(NTHREADS, 2)
cell_mma(const __nv_bfloat16* __restrict__ AhH, const __nv_bfloat16* __restrict__ AhL,
         const __nv_bfloat16* __restrict__ BhH, const __nv_bfloat16* __restrict__ BhL,
         const __nv_bfloat16* __restrict__ AxH, const __nv_bfloat16* __restrict__ AxL,
         const __nv_bfloat16* __restrict__ BxH, const __nv_bfloat16* __restrict__ BxL,
         int ncx, int ldx,
         const float* __restrict__ biasr,
         float* __restrict__ c, float* __restrict__ hf,
         __nv_bfloat16* __restrict__ hhi, __nv_bfloat16* __restrict__ hlo) {
    extern __shared__ __align__(16) char smem[];
    cell_body<32>(smem, blockIdx.x * 32, blockIdx.y,
                  AhH, AhL, BhH, BhL, AxH, AxL, BxH, BxL,
                  ncx, ldx, biasr, c, hf, hhi, hlo);
}

// ---------------------------------------------------------------------------
// Merged encoder wavefront step: MT=64, grid (4,64)=256 CTAs, 2/SM resident.
// L1(t) on tiles y<32, L0(t+1) on tiles y>=32.
// ---------------------------------------------------------------------------
__global__ void __launch_bounds__(NTHREADS, 2)
enc_step(// L1(t):
         const __nv_bfloat16* __restrict__ h1pH, const __nv_bfloat16* __restrict__ h1pL,
         const __nv_bfloat16* __restrict__ w1hhh, const __nv_bfloat16* __restrict__ w1hhl,
         const __nv_bfloat16* __restrict__ y0tH, const __nv_bfloat16* __restrict__ y0tL,
         const __nv_bfloat16* __restrict__ w1ihh, const __nv_bfloat16* __restrict__ w1ihl,
         const float* __restrict__ br1, float* __restrict__ c1,
         float* __restrict__ h1f,
         __nv_bfloat16* __restrict__ h1oh, __nv_bfloat16* __restrict__ h1ol,
         // L0(t+1):
         const __nv_bfloat16* __restrict__ xnH, const __nv_bfloat16* __restrict__ xnL,
         const __nv_bfloat16* __restrict__ w0h, const __nv_bfloat16* __restrict__ w0l,
         const __nv_bfloat16* __restrict__ wx0h, const __nv_bfloat16* __restrict__ wx0l,
         const float* __restrict__ br0, float* __restrict__ c0,
         float* __restrict__ h0f,
         __nv_bfloat16* __restrict__ y0nH, __nv_bfloat16* __restrict__ y0nL) {
    extern __shared__ __align__(16) char smem[];
    const int m0 = blockIdx.x * 64;
    if (blockIdx.y < 32) {
        cell_body<64>(smem, m0, blockIdx.y,
                      h1pH, h1pL, w1hhh, w1hhl, y0tH, y0tL, w1ihh, w1ihl,
                      8, HID, br1, c1, h1f, h1oh, h1ol);
    } else {
        cell_body<64>(smem, m0, blockIdx.y - 32,
                      y0tH, y0tL, w0h, w0l, xnH, xnL, wx0h, wx0l,
                      1, XPW, br0, c0, h0f, y0nH, y0nL);
    }
}

// ---------------------------------------------------------------------------
// head: pred += h1 @ headW^T + headb ; write output[t]; build next decoder x
// ---------------------------------------------------------------------------
__global__ void head_kernel(const float* __restrict__ h1,
                            const float* __restrict__ headW,
                            const float* __restrict__ headb,
                            float* __restrict__ pred,
                            float* __restrict__ out_t,
                            const float* __restrict__ wf_next,
                            __nv_bfloat16* __restrict__ xdh,
                            __nv_bfloat16* __restrict__ xdl) {
    int b = blockIdx.x;
    int w = threadIdx.x >> 5;
    int lane = threadIdx.x & 31;
    const float* hr = &h1[b * HID];
    const float* wr = &headW[w * HID];
    float s = 0.f;
    for (int k = lane; k < HID; k += 32) s += hr[k] * wr[k];
#pragma unroll
    for (int o = 16; o; o >>= 1) s += __shfl_down_sync(0xffffffffu, s, o);
    if (lane == 0) {
        float p = pred[b * VEG + w] + s + headb[w];
        pred[b * VEG + w] = p;
        out_t[b * (T_FUT * VEG) + w] = p;
        __nv_bfloat16 hh, ll; split2(p, hh, ll);
        xdh[b * XPW + w] = hh; xdl[b * XPW + w] = ll;
    }
    if (threadIdx.x < WEA && wf_next) {
        float v = wf_next[b * (T_FUT * WEA) + threadIdx.x];
        __nv_bfloat16 hh, ll; split2(v, hh, ll);
        xdh[b * XPW + VEG + threadIdx.x] = hh;
        xdl[b * XPW + VEG + threadIdx.x] = ll;
    }
}

// ---------------------------------------------------------------------------
// Host launcher (single stream — graph-capture safe)
// ---------------------------------------------------------------------------
extern "C" void kernel_launch(void* const* d_in, const int* in_sizes, int n_in,
                              void* d_out, int out_size) {
    const float* veg   = (const float*)d_in[0];
    const float* wh    = (const float*)d_in[1];
    const float* wf    = (const float*)d_in[2];
    const float* Wih0  = (const float*)d_in[3];
    const float* Whh0  = (const float*)d_in[4];
    const float* b0    = (const float*)d_in[5];
    const float* Wih1  = (const float*)d_in[6];
    const float* Whh1  = (const float*)d_in[7];
    const float* b1    = (const float*)d_in[8];
    const float* headW = (const float*)d_in[9];
    const float* headb = (const float*)d_in[10];
    float* out = (float*)d_out;

    __nv_bfloat16 *xph, *xpl, *xdh, *xdl, *y0h, *y0l, *zb;
    __nv_bfloat16 *h1h, *h1l, *h0h, *h0l;
    __nv_bfloat16 *w0h, *w0l, *w1hhh, *w1hhl, *w1ihh, *w1ihl, *wx0h, *wx0l;
    float *pred, *c0, *c1, *h1f, *h0f, *br0, *br1;
    cudaGetSymbolAddress((void**)&xph,   g_xph);
    cudaGetSymbolAddress((void**)&xpl,   g_xpl);
    cudaGetSymbolAddress((void**)&xdh,   g_xdh);
    cudaGetSymbolAddress((void**)&xdl,   g_xdl);
    cudaGetSymbolAddress((void**)&pred,  g_pred);
    cudaGetSymbolAddress((void**)&y0h,   g_y0h);
    cudaGetSymbolAddress((void**)&y0l,   g_y0l);
    cudaGetSymbolAddress((void**)&zb,    g_zb);
    cudaGetSymbolAddress((void**)&c0,    g_c0);
    cudaGetSymbolAddress((void**)&c1,    g_c1);
    cudaGetSymbolAddress((void**)&h1h,   g_h1h);
    cudaGetSymbolAddress((void**)&h1l,   g_h1l);
    cudaGetSymbolAddress((void**)&h0h,   g_h0h);
    cudaGetSymbolAddress((void**)&h0l,   g_h0l);
    cudaGetSymbolAddress((void**)&h1f,   g_h1f);
    cudaGetSymbolAddress((void**)&h0f,   g_h0f);
    cudaGetSymbolAddress((void**)&w0h,   g_w0h);
    cudaGetSymbolAddress((void**)&w0l,   g_w0l);
    cudaGetSymbolAddress((void**)&w1hhh, g_w1hh_h);
    cudaGetSymbolAddress((void**)&w1hhl, g_w1hh_l);
    cudaGetSymbolAddress((void**)&w1ihh, g_w1ih_h);
    cudaGetSymbolAddress((void**)&w1ihl, g_w1ih_l);
    cudaGetSymbolAddress((void**)&wx0h,  g_wx0h);
    cudaGetSymbolAddress((void**)&wx0l,  g_wx0l);
    cudaGetSymbolAddress((void**)&br0,   g_br0);
    cudaGetSymbolAddress((void**)&br1,   g_br1);

    cudaFuncSetAttribute(cell_mma, cudaFuncAttributeMaxDynamicSharedMemorySize,
                         SMEM_TOTAL_(32));
    cudaFuncSetAttribute(enc_step, cudaFuncAttributeMaxDynamicSharedMemorySize,
                         SMEM_TOTAL_(64));

    dim3 grid1(8, 32), grid2(4, 64), blk(NTHREADS);

    prep_kernel<<<T_HIST, NB>>>(veg, wh, wf, xph, xpl, xdh, xdl, pred);
    wprep_kernel<<<GROW, 128>>>(Wih0, Whh0, b0, Wih1, Whh1, b1,
                                w0h, w0l, w1hhh, w1hhl, w1ihh, w1ihl,
                                wx0h, wx0l, br0, br1);
    zero_kernel<<<(HB + 255) / 256, 256>>>(c0, c1, zb);

    // L0(0) alone
    cell_mma<<<grid1, blk, SMEM_TOTAL_(32)>>>(
        zb, zb, w0h, w0l, xph, xpl, wx0h, wx0l,
        1, XPW, br0, c0, h0f, y0h, y0l);

    // merged wavefront: t = 0..148 computes L1(t) and L0(t+1) concurrently
    for (int t = 0; t < T_HIST - 1; t++) {
        const __nv_bfloat16* h1pH = (t == 0) ? zb : (h1h + ((t + 1) & 1) * HB);
        const __nv_bfloat16* h1pL = (t == 0) ? zb : (h1l + ((t + 1) & 1) * HB);
        enc_step<<<grid2, blk, SMEM_TOTAL_(64)>>>(
            h1pH, h1pL, w1hhh, w1hhl,
            y0h + (size_t)t * HB, y0l + (size_t)t * HB, w1ihh, w1ihl,
            br1, c1, h1f, h1h + (t & 1) * HB, h1l + (t & 1) * HB,
            xph + (size_t)(t + 1) * NB * XPW, xpl + (size_t)(t + 1) * NB * XPW,
            w0h, w0l, wx0h, wx0l,
            br0, c0, h0f,
            y0h + (size_t)(t + 1) * HB, y0l + (size_t)(t + 1) * HB);
    }
    // final L1(149): reads h1[148&1=0], writes h1[149&1=1]
    {
        int t = T_HIST - 1;
        cell_mma<<<grid1, blk, SMEM_TOTAL_(32)>>>(
            h1h + ((t + 1) & 1) * HB, h1l + ((t + 1) & 1) * HB, w1hhh, w1hhl,
            y0h + (size_t)t * HB, y0l + (size_t)t * HB, w1ihh, w1ihl,
            8, HID, br1, c1, h1f, h1h + (t & 1) * HB, h1l + (t & 1) * HB);
    }

    // decoder (serial dependence); h1 phases: read (t+1)&1, write t&1
    for (int t = 0; t < T_FUT; t++) {
        const __nv_bfloat16* hpH = (t == 0) ? (y0h + (size_t)(T_HIST - 1) * HB)
                                            : (h0h + ((t + 1) & 1) * HB);
        const __nv_bfloat16* hpL = (t == 0) ? (y0l + (size_t)(T_HIST - 1) * HB)
                                            : (h0l + ((t + 1) & 1) * HB);
        cell_mma<<<grid1, blk, SMEM_TOTAL_(32)>>>(
            hpH, hpL, w0h, w0l, xdh, xdl, wx0h, wx0l,
            1, XPW, br0, c0, h0f, h0h + (t & 1) * HB, h0l + (t & 1) * HB);
        cell_mma<<<grid1, blk, SMEM_TOTAL_(32)>>>(
            h1h + ((t + 1) & 1) * HB, h1l + ((t + 1) & 1) * HB, w1hhh, w1hhl,
            h0h + (t & 1) * HB, h0l + (t & 1) * HB, w1ihh, w1ihl,
            8, HID, br1, c1, h1f, h1h + (t & 1) * HB, h1l + (t & 1) * HB);
        const float* wfn = (t < T_FUT - 1) ? (wf + (t + 1) * WEA) : nullptr;
        head_kernel<<<NB, 128>>>(h1f, headW, headb, pred,
                                 out + t * VEG, wfn, xdh, xdl);
    }
}